// round 14
// baseline (speedup 1.0000x reference)
#include <cuda_runtime.h>
#include <cuda_fp16.h>
#include <cstdint>

#define BB    16
#define HH    512
#define WW    512
#define HW    (HH * WW)
#define NPIX  (BB * HW)

#define RSTR  520                       // padded row stride
#define FPAD  528                       // per-image front pad
#define BPAD  528                       // per-image back pad
#define IMG   (FPAD + HH * RSTR + BPAD)
#define PTOT  (BB * IMG)

#define SMS   520                       // smem strip row stride (floats)
#define FTHR  384                       // fused3 block size

typedef unsigned int u32;

// A planes: padded; pads/gaps initialized to 1.0 (OOB softmax entry = exp(0)=1,
// so inline-S sums are exact at boundaries). Message terms at OOB multiply by
// pred=0 (g_buf pads stay zero-initialized, never written).
// Dirs: 0=(0,1) 1=(1,-1) 2=(1,0) 3=(1,1);  A = exp(entry), symmetric:
// A_d(p) == A_{-d}(p+d); center entry = exp(1).
__device__ __half g_A[4][PTOT];    // 34.2 MB
__device__ float  g_buf[2][PTOT];  // padded ping-pong pred buffers

#define AC 2.7182818284590452f     // exp(1): center softmax-numerator

// ---------------------------------------------------------------------------
__device__ __forceinline__ float2 h2f(const u32 u) {
    return __half22float2(*reinterpret_cast<const __half2*>(&u));
}
__device__ __forceinline__ u32 pack2(float a, float b) {
    __half2 h = __halves2half2(__float2half(a), __float2half(b));
    return *reinterpret_cast<u32*>(&h);
}
__device__ __forceinline__ void unpack8(const uint4 v, float* f) {
    float2 a = h2f(v.x), b = h2f(v.y), c = h2f(v.z), d = h2f(v.w);
    f[0] = a.x; f[1] = a.y; f[2] = b.x; f[3] = b.y;
    f[4] = c.x; f[5] = c.y; f[6] = d.x; f[7] = d.y;
}
// CSE-proof vector load (for deliberate L1-hot reloads)
__device__ __forceinline__ uint4 ldg4v(const void* p) {
    uint4 v;
    asm volatile("ld.global.nc.v4.u32 {%0,%1,%2,%3}, [%4];"
        : "=r"(v.x), "=r"(v.y), "=r"(v.z), "=r"(v.w) : "l"(p));
    return v;
}
// r[0..9] = p[-1..8]   (only for pointers where p[-1]/p[8] are in-bounds!)
__device__ __forceinline__ void ldrow(const float* p, float* r) {
    float4 v0 = *(const float4*)p;
    float4 v1 = *(const float4*)(p + 4);
    r[0] = p[-1];
    r[1] = v0.x; r[2] = v0.y; r[3] = v0.z; r[4] = v0.w;
    r[5] = v1.x; r[6] = v1.y; r[7] = v1.z; r[8] = v1.w;
    r[9] = p[8];
}
// guarded variant for UNPADDED arrays: edge scalars zeroed at image borders
__device__ __forceinline__ void ldrow_g(const float* p, float* r, int w8) {
    float4 v0 = *(const float4*)p;
    float4 v1 = *(const float4*)(p + 4);
    r[0] = (w8 > 0)      ? p[-1] : 0.0f;
    r[1] = v0.x; r[2] = v0.y; r[3] = v0.z; r[4] = v0.w;
    r[5] = v1.x; r[6] = v1.y; r[7] = v1.z; r[8] = v1.w;
    r[9] = (w8 + 8 < WW) ? p[8]  : 0.0f;
}
__device__ __forceinline__ void st8(float* d, const float* o) {
    *(float4*)d       = make_float4(o[0], o[1], o[2], o[3]);
    *(float4*)(d + 4) = make_float4(o[4], o[5], o[6], o[7]);
}
__device__ __forceinline__ void stz8(float* d) {
    *(float4*)d       = make_float4(0.f, 0.f, 0.f, 0.f);
    *(float4*)(d + 4) = make_float4(0.f, 0.f, 0.f, 0.f);
}

// ---------------------------------------------------------------------------
// Set A pads/gaps (front pad, per-row 8-elem gaps, back pad) to 1.0.
// ---------------------------------------------------------------------------
#define PADN (FPAD + HH * 8 + BPAD)     // pad elems per image
__global__ __launch_bounds__(256)
void init_pads()
{
    int e = blockIdx.x * 256 + threadIdx.x;
    if (e >= BB * PADN) return;
    int b = e / PADN, j = e - b * PADN;
    int off;
    if (j < FPAD)             off = j;
    else if (j < FPAD + HH*8) { int g = j - FPAD; off = FPAD + (g >> 3) * RSTR + WW + (g & 7); }
    else                      off = FPAD + HH * RSTR + (j - (FPAD + HH * 8));
    const __half one = __float2half(1.0f);
    int idx = b * IMG + off;
    g_A[0][idx] = one; g_A[1][idx] = one; g_A[2][idx] = one; g_A[3][idx] = one;
}

// ---------------------------------------------------------------------------
// Build pass + iteration 1, octet-per-thread, vectorized windows.
// ---------------------------------------------------------------------------
__global__ __launch_bounds__(256)
void build_kernel(const float* __restrict__ image,
                  const float* __restrict__ unary,
                  const float* __restrict__ theta,
                  const float* __restrict__ weight,
                  float* __restrict__ pout)
{
    int t  = blockIdx.x * 256 + threadIdx.x;
    int w8 = (t & 63) << 3;
    int h  = (t >> 6) & (HH - 1);
    int b  = t >> 15;
    int uidx = b * HW + (h << 9) + w8;

    float t0 = theta[0], t1 = theta[1], t2 = theta[2];
    float hw = 0.5f * weight[0];

    float win[3][10], uwin[3][10];
    bool rowok[3];
#pragma unroll
    for (int r = 0; r < 3; r++) {
        int gh = h + r - 1;
        rowok[r] = (unsigned)gh < HH;
        if (!rowok[r]) {
#pragma unroll
            for (int c = 0; c < 10; c++) { win[r][c] = 0.f; uwin[r][c] = 0.f; }
        } else {
            ldrow_g(image + uidx + (r - 1) * WW, win[r],  w8);
            ldrow_g(unary + uidx + (r - 1) * WW, uwin[r], w8);
        }
    }

    float geo[9];
#pragma unroll
    for (int k = 0; k < 9; k++) {
        int dx = k / 3 - 1, dy = k % 3 - 1;
        geo[k] = t0 * (float)(dx * dx) + t1 * (float)(dy * dy);
    }

    float A5[8], A6[8], A7[8], A8[8], outv[8];
#pragma unroll
    for (int j = 0; j < 8; j++) {
        float cc = win[1][j + 1] * 255.f;
        float S = AC, msg = 0.f;
#pragma unroll
        for (int k = 0; k < 9; k++) {
            int dx = k / 3 - 1, dy = k % 3 - 1;
            bool ok = rowok[1 + dx];
            if (dy < 0) ok = ok && (w8 + j > 0);
            if (dy > 0) ok = ok && (w8 + j + 1 < WW);
            float nb = win[1 + dx][j + 1 + dy];
            float d  = nb * 255.f - cc;
            float e  = ok ? __expf(-0.5f * (geo[k] + t2 * d * d)) : 0.f;
            float Af = __expf(e);
            if (k != 4) S += __half2float(__float2half(Af));
            msg += Af * uwin[1 + dx][j + 1 + dy];   // OOB: 1 * 0 = 0
            if (k == 5) A5[j] = Af;
            if (k == 6) A6[j] = Af;
            if (k == 7) A7[j] = Af;
            if (k == 8) A8[j] = Af;
        }
        outv[j] = 0.5f * uwin[1][j + 1] + __fdividef(hw, S) * msg;
    }

    int pidx = b * IMG + FPAD + h * RSTR + w8;
    uint4 v;
    v.x = pack2(A5[0], A5[1]); v.y = pack2(A5[2], A5[3]);
    v.z = pack2(A5[4], A5[5]); v.w = pack2(A5[6], A5[7]);
    *(uint4*)&g_A[0][pidx] = v;
    v.x = pack2(A6[0], A6[1]); v.y = pack2(A6[2], A6[3]);
    v.z = pack2(A6[4], A6[5]); v.w = pack2(A6[6], A6[7]);
    *(uint4*)&g_A[1][pidx] = v;
    v.x = pack2(A7[0], A7[1]); v.y = pack2(A7[2], A7[3]);
    v.z = pack2(A7[4], A7[5]); v.w = pack2(A7[6], A7[7]);
    *(uint4*)&g_A[2][pidx] = v;
    v.x = pack2(A8[0], A8[1]); v.y = pack2(A8[2], A8[3]);
    v.z = pack2(A8[4], A8[5]); v.w = pack2(A8[6], A8[7]);
    *(uint4*)&g_A[3][pidx] = v;
    st8(pout + pidx, outv);
}

// ---------------------------------------------------------------------------
// Two adjacent Jacobi rows (gh, gh+1) x 8 cols. Register-lean ordering:
// each pred row is consumed immediately; row-A forward planes are reloaded
// (CSE-proof, L1-hot) at second use instead of persisting 24 floats;
// unary loads moved to the epilogue.
// ---------------------------------------------------------------------------
__device__ __forceinline__ void jac2(
    int pidxA, int uidx,
    const float* p0, const float* p1, const float* p2, const float* p3,
    const float* __restrict__ unary, float hw, float* oA, float* oB)
{
    const __half* P0 = g_A[0]; const __half* P1 = g_A[1];
    const __half* P2 = g_A[2]; const __half* P3 = g_A[3];
    int pidxB = pidxA + RSTR, up = pidxA - RSTR;

    float SA[8], SB[8], accA[8], accB[8];

    // step 1: pred row gh-1 -> row A backward terms (dirs 1,2,3)
    {
        float r[10]; ldrow(p0, r);
        uint4 U1v = __ldg((const uint4*)&P1[up]);
        uint4 U2v = __ldg((const uint4*)&P2[up]);
        uint4 U3v = __ldg((const uint4*)&P3[up]);
        float e1 = h2f(__ldg((const u32*)&P1[up + 8])).x;
        float e3 = h2f(__ldg((const u32*)&P3[up - 2])).y;
        float u1[8], u2[8], u3[8];
        unpack8(U1v, u1); unpack8(U2v, u2); unpack8(U3v, u3);
#pragma unroll
        for (int j = 0; j < 8; j++) {
            float b1 = (j < 7) ? u1[j + 1] : e1;
            float b3 = (j > 0) ? u3[j - 1] : e3;
            accA[j] = b1 * r[j + 2] + u2[j] * r[j + 1] + b3 * r[j];
            SA[j]   = b1 + u2[j] + b3;
        }
    }
    // step 2: pred row gh -> row A center+dir0; row B backward terms
    {
        float r[10]; ldrow(p1, r);
        {
            float f0[8]; unpack8(__ldg((const uint4*)&P0[pidxA]), f0);
            float b0a = h2f(__ldg((const u32*)&P0[pidxA - 2])).y;
#pragma unroll
            for (int j = 0; j < 8; j++) {
                float bw0 = (j > 0) ? f0[j - 1] : b0a;
                accA[j] += AC * r[j + 1] + f0[j] * r[j + 2] + bw0 * r[j];
                SA[j]   += f0[j] + bw0;
            }
        }
        {
            float f1[8], f2[8], f3[8];
            unpack8(__ldg((const uint4*)&P1[pidxA]), f1);
            unpack8(__ldg((const uint4*)&P2[pidxA]), f2);
            unpack8(__ldg((const uint4*)&P3[pidxA]), f3);
            float e1a = h2f(__ldg((const u32*)&P1[pidxA + 8])).x;
            float e3a = h2f(__ldg((const u32*)&P3[pidxA - 2])).y;
#pragma unroll
            for (int j = 0; j < 8; j++) {
                float b1 = (j < 7) ? f1[j + 1] : e1a;
                float b3 = (j > 0) ? f3[j - 1] : e3a;
                accB[j] = b1 * r[j + 2] + f2[j] * r[j + 1] + b3 * r[j];
                SB[j]   = b1 + f2[j] + b3;
            }
        }
    }
    // step 3: pred row gh+1 -> row A forward (reload planes, L1-hot);
    //         row B center+dir0
    {
        float r[10]; ldrow(p2, r);
        {
            float f1[8], f2[8], f3[8];
            unpack8(ldg4v(&P1[pidxA]), f1);
            unpack8(ldg4v(&P2[pidxA]), f2);
            unpack8(ldg4v(&P3[pidxA]), f3);
#pragma unroll
            for (int j = 0; j < 8; j++) {
                accA[j] += f1[j] * r[j] + f2[j] * r[j + 1] + f3[j] * r[j + 2];
                SA[j]   += f1[j] + f2[j] + f3[j];
            }
        }
        {
            float f0[8]; unpack8(__ldg((const uint4*)&P0[pidxB]), f0);
            float b0b = h2f(__ldg((const u32*)&P0[pidxB - 2])).y;
#pragma unroll
            for (int j = 0; j < 8; j++) {
                float bw0 = (j > 0) ? f0[j - 1] : b0b;
                accB[j] += AC * r[j + 1] + f0[j] * r[j + 2] + bw0 * r[j];
                SB[j]   += f0[j] + bw0;
            }
        }
    }
    // step 4: pred row gh+2 -> row B forward terms
    {
        float r[10]; ldrow(p3, r);
        float f1[8], f2[8], f3[8];
        unpack8(__ldg((const uint4*)&P1[pidxB]), f1);
        unpack8(__ldg((const uint4*)&P2[pidxB]), f2);
        unpack8(__ldg((const uint4*)&P3[pidxB]), f3);
#pragma unroll
        for (int j = 0; j < 8; j++) {
            accB[j] += f1[j] * r[j] + f2[j] * r[j + 1] + f3[j] * r[j + 2];
            SB[j]   += f1[j] + f2[j] + f3[j];
        }
    }
    // epilogue: unary + normalize
    {
        float4 ua0 = __ldg((const float4*)(unary + uidx));
        float4 ua1 = __ldg((const float4*)(unary + uidx + 4));
        float unA[8] = {ua0.x, ua0.y, ua0.z, ua0.w, ua1.x, ua1.y, ua1.z, ua1.w};
#pragma unroll
        for (int j = 0; j < 8; j++)
            oA[j] = 0.5f * unA[j] + __fdividef(hw, AC + SA[j]) * accA[j];
    }
    {
        float4 ub0 = __ldg((const float4*)(unary + uidx + WW));
        float4 ub1 = __ldg((const float4*)(unary + uidx + WW + 4));
        float unB[8] = {ub0.x, ub0.y, ub0.z, ub0.w, ub1.x, ub1.y, ub1.z, ub1.w};
#pragma unroll
        for (int j = 0; j < 8; j++)
            oB[j] = 0.5f * unB[j] + __fdividef(hw, AC + SB[j]) * accB[j];
    }
}

// ---------------------------------------------------------------------------
// Fused 3 iterations on a 16-row x 512-col strip, 2-row groups.
// bufA rows R-2..R+17 (20), bufB rows R-1..R+16 (18); guards at cols 3/516.
// 384 threads, 2 blocks/SM (regs capped at 85; smem 2x79KB fits 228KB).
// ---------------------------------------------------------------------------
__global__ __launch_bounds__(FTHR, 2)
void fused3(const float* __restrict__ pin,
            const float* __restrict__ unary,
            const float* __restrict__ weight,
            float* __restrict__ pout, int last)
{
    extern __shared__ float sm[];
    float* bufA = sm;                  // 20 x SMS
    float* bufB = sm + 20 * SMS;       // 18 x SMS

    int tid = threadIdx.x;
    int blk = blockIdx.x;
    int b   = blk >> 5;
    int R   = (blk & 31) << 4;
    float hw = 0.5f * __ldg(weight);

    if (tid < 20)      { bufA[tid * SMS + 3] = 0.f; bufA[tid * SMS + 516] = 0.f; }
    else if (tid < 38) { int i = tid - 20;
                         bufB[i * SMS + 3] = 0.f; bufB[i * SMS + 516] = 0.f; }

    // phase 1: rows R-2..R+17 (10 groups x 64 cols) from global -> bufA
    for (int g = tid; g < 640; g += FTHR) {
        int gi = g >> 6, c = (g & 63) << 3;
        int gh = R - 2 + gi * 2;
        float* dA0 = &bufA[(gi * 2) * SMS + 4 + c];
        if ((unsigned)gh < HH) {
            int pidxA = b * IMG + FPAD + gh * RSTR + c;
            int uidx  = b * HW + (gh << 9) + c;
            const float* pb = pin + pidxA;
            float oA[8], oB[8];
            jac2(pidxA, uidx, pb - RSTR, pb, pb + RSTR, pb + 2 * RSTR,
                 unary, hw, oA, oB);
            st8(dA0, oA); st8(dA0 + SMS, oB);
        } else { stz8(dA0); stz8(dA0 + SMS); }
    }
    __syncthreads();

    // phase 2: 10 groups covering rows R-2..R+17; keep rows R-1..R+16 -> bufB
    for (int g = tid; g < 640; g += FTHR) {
        int gi = g >> 6, c = (g & 63) << 3;
        int gh = R - 2 + gi * 2;
        int jB0 = 2 * gi - 1, jB1 = 2 * gi;
        bool w0 = (gi > 0), w1 = (gi < 9);
        if ((unsigned)gh < HH) {
            int pidxA = b * IMG + FPAD + gh * RSTR + c;
            int uidx  = b * HW + (gh << 9) + c;
            int iA = 2 * gi;
            const float* q0 = &bufA[(iA > 0 ? iA - 1 : 0) * SMS + 4 + c];
            const float* q1 = &bufA[iA * SMS + 4 + c];
            const float* q2 = &bufA[(iA + 1) * SMS + 4 + c];
            const float* q3 = &bufA[(iA + 2 < 20 ? iA + 2 : 19) * SMS + 4 + c];
            float oA[8], oB[8];
            jac2(pidxA, uidx, q0, q1, q2, q3, unary, hw, oA, oB);
            if (w0) st8(&bufB[jB0 * SMS + 4 + c], oA);
            if (w1) st8(&bufB[jB1 * SMS + 4 + c], oB);
        } else {
            if (w0) stz8(&bufB[jB0 * SMS + 4 + c]);
            if (w1) stz8(&bufB[jB1 * SMS + 4 + c]);
        }
    }
    __syncthreads();

    // phase 3: rows R..R+15 (8 groups x 64 cols = 512 items) -> global
    for (int g = tid; g < 512; g += FTHR) {
        int gi = g >> 6, c = (g & 63) << 3;
        int gh = R + 2 * gi;
        int pidxA = b * IMG + FPAD + gh * RSTR + c;
        int uidx  = b * HW + (gh << 9) + c;
        int iB = 2 * gi + 1;
        const float* q0 = &bufB[(iB - 1) * SMS + 4 + c];
        const float* q1 = &bufB[iB * SMS + 4 + c];
        const float* q2 = &bufB[(iB + 1) * SMS + 4 + c];
        const float* q3 = &bufB[(iB + 2) * SMS + 4 + c];
        float oA[8], oB[8];
        jac2(pidxA, uidx, q0, q1, q2, q3, unary, hw, oA, oB);
        if (last) {
            st8(pout + uidx, oA);
            st8(pout + uidx + WW, oB);
        } else {
            st8(pout + pidxA, oA);
            st8(pout + pidxA + RSTR, oB);
        }
    }
}

extern "C" void kernel_launch(void* const* d_in, const int* in_sizes, int n_in,
                              void* d_out, int out_size)
{
    const float* image  = (const float*)d_in[0];
    const float* unary  = (const float*)d_in[1];
    const float* theta  = (const float*)d_in[2];
    const float* weight = (const float*)d_in[3];
    float* out = (float*)d_out;

    void* baddr = nullptr;
    cudaGetSymbolAddress(&baddr, g_buf);   // non-stream API: capture-safe
    float* buf0 = (float*)baddr;
    float* buf1 = buf0 + PTOT;

    const int SMEM = (20 + 18) * SMS * (int)sizeof(float);   // 79,040 B
    cudaFuncSetAttribute(fused3, cudaFuncAttributeMaxDynamicSharedMemorySize, SMEM);

    init_pads<<<(BB * PADN + 255) / 256, 256>>>();
    build_kernel<<<(NPIX / 8) / 256, 256>>>(image, unary, theta, weight, buf0); // +iter1
    fused3<<<BB * 32, FTHR, SMEM>>>(buf0, unary, weight, buf1, 0);   // iters 2-4
    fused3<<<BB * 32, FTHR, SMEM>>>(buf1, unary, weight, buf0, 0);   // iters 5-7
    fused3<<<BB * 32, FTHR, SMEM>>>(buf0, unary, weight, out, 1);    // iters 8-10
}

// round 15
// speedup vs baseline: 1.0595x; 1.0595x over previous
#include <cuda_runtime.h>
#include <cuda_fp16.h>
#include <cstdint>

#define BB    16
#define HH    512
#define WW    512
#define HW    (HH * WW)
#define NPIX  (BB * HW)

#define RSTR  520                       // padded row stride
#define FPAD  528                       // per-image front pad
#define BPAD  528                       // per-image back pad
#define IMG   (FPAD + HH * RSTR + BPAD)
#define PTOT  (BB * IMG)

typedef unsigned int u32;

// A planes: padded, plane-major; pads/gaps = 1.0 (OOB softmax entry = exp(0),
// so inline-S is exact at borders). Pred buffers padded, pads stay 0.0
// (zero-initialized device globals, never written) -> message terms at OOB
// multiply by pred=0: exact reference boundary semantics, zero predicates.
// Dirs: 0=(0,1) 1=(1,-1) 2=(1,0) 3=(1,1);  A = exp(entry), symmetric:
// A_d(p) == A_{-d}(p+d); center entry = exp(1).
__device__ __half g_A[4][PTOT];    // 34.2 MB
__device__ float  g_buf[2][PTOT];  // padded ping-pong pred buffers

#define AC 2.7182818284590452f     // exp(1): center softmax-numerator

// ---------------------------------------------------------------------------
__device__ __forceinline__ float2 h2f(const u32 u) {
    return __half22float2(*reinterpret_cast<const __half2*>(&u));
}
__device__ __forceinline__ u32 pack2(float a, float b) {
    __half2 h = __halves2half2(__float2half(a), __float2half(b));
    return *reinterpret_cast<u32*>(&h);
}
__device__ __forceinline__ void unpack4(const uint2 v, float* f) {
    float2 a = h2f(v.x), b = h2f(v.y);
    f[0] = a.x; f[1] = a.y; f[2] = b.x; f[3] = b.y;
}
// guarded row load for UNPADDED arrays: edge scalars zeroed at image borders
__device__ __forceinline__ void ldrow_g(const float* p, float* r, int w8) {
    float4 v0 = *(const float4*)p;
    float4 v1 = *(const float4*)(p + 4);
    r[0] = (w8 > 0)      ? p[-1] : 0.0f;
    r[1] = v0.x; r[2] = v0.y; r[3] = v0.z; r[4] = v0.w;
    r[5] = v1.x; r[6] = v1.y; r[7] = v1.z; r[8] = v1.w;
    r[9] = (w8 + 8 < WW) ? p[8]  : 0.0f;
}
__device__ __forceinline__ void st8(float* d, const float* o) {
    *(float4*)d       = make_float4(o[0], o[1], o[2], o[3]);
    *(float4*)(d + 4) = make_float4(o[4], o[5], o[6], o[7]);
}

// ---------------------------------------------------------------------------
// Set A pads/gaps (front pad, per-row 8-elem gaps, back pad) to 1.0.
// ---------------------------------------------------------------------------
#define PADN (FPAD + HH * 8 + BPAD)     // pad elems per image
__global__ __launch_bounds__(256)
void init_pads()
{
    int e = blockIdx.x * 256 + threadIdx.x;
    if (e >= BB * PADN) return;
    int b = e / PADN, j = e - b * PADN;
    int off;
    if (j < FPAD)             off = j;
    else if (j < FPAD + HH*8) { int g = j - FPAD; off = FPAD + (g >> 3) * RSTR + WW + (g & 7); }
    else                      off = FPAD + HH * RSTR + (j - (FPAD + HH * 8));
    const __half one = __float2half(1.0f);
    int idx = b * IMG + off;
    g_A[0][idx] = one; g_A[1][idx] = one; g_A[2][idx] = one; g_A[3][idx] = one;
}

// ---------------------------------------------------------------------------
// Build pass + iteration 1, octet-per-thread (verified in round 13/14).
// ---------------------------------------------------------------------------
__global__ __launch_bounds__(256)
void build_kernel(const float* __restrict__ image,
                  const float* __restrict__ unary,
                  const float* __restrict__ theta,
                  const float* __restrict__ weight,
                  float* __restrict__ pout)
{
    int t  = blockIdx.x * 256 + threadIdx.x;
    int w8 = (t & 63) << 3;
    int h  = (t >> 6) & (HH - 1);
    int b  = t >> 15;
    int uidx = b * HW + (h << 9) + w8;

    float t0 = theta[0], t1 = theta[1], t2 = theta[2];
    float hw = 0.5f * weight[0];

    float win[3][10], uwin[3][10];
    bool rowok[3];
#pragma unroll
    for (int r = 0; r < 3; r++) {
        int gh = h + r - 1;
        rowok[r] = (unsigned)gh < HH;
        if (!rowok[r]) {
#pragma unroll
            for (int c = 0; c < 10; c++) { win[r][c] = 0.f; uwin[r][c] = 0.f; }
        } else {
            ldrow_g(image + uidx + (r - 1) * WW, win[r],  w8);
            ldrow_g(unary + uidx + (r - 1) * WW, uwin[r], w8);
        }
    }

    float geo[9];
#pragma unroll
    for (int k = 0; k < 9; k++) {
        int dx = k / 3 - 1, dy = k % 3 - 1;
        geo[k] = t0 * (float)(dx * dx) + t1 * (float)(dy * dy);
    }

    float A5[8], A6[8], A7[8], A8[8], outv[8];
#pragma unroll
    for (int j = 0; j < 8; j++) {
        float cc = win[1][j + 1] * 255.f;
        float S = AC, msg = 0.f;
#pragma unroll
        for (int k = 0; k < 9; k++) {
            int dx = k / 3 - 1, dy = k % 3 - 1;
            bool ok = rowok[1 + dx];
            if (dy < 0) ok = ok && (w8 + j > 0);
            if (dy > 0) ok = ok && (w8 + j + 1 < WW);
            float nb = win[1 + dx][j + 1 + dy];
            float d  = nb * 255.f - cc;
            float e  = ok ? __expf(-0.5f * (geo[k] + t2 * d * d)) : 0.f;
            float Af = __expf(e);
            if (k != 4) S += __half2float(__float2half(Af));
            msg += Af * uwin[1 + dx][j + 1 + dy];   // OOB: 1 * 0 = 0
            if (k == 5) A5[j] = Af;
            if (k == 6) A6[j] = Af;
            if (k == 7) A7[j] = Af;
            if (k == 8) A8[j] = Af;
        }
        outv[j] = 0.5f * uwin[1][j + 1] + __fdividef(hw, S) * msg;
    }

    int pidx = b * IMG + FPAD + h * RSTR + w8;
    uint4 v;
    v.x = pack2(A5[0], A5[1]); v.y = pack2(A5[2], A5[3]);
    v.z = pack2(A5[4], A5[5]); v.w = pack2(A5[6], A5[7]);
    *(uint4*)&g_A[0][pidx] = v;
    v.x = pack2(A6[0], A6[1]); v.y = pack2(A6[2], A6[3]);
    v.z = pack2(A6[4], A6[5]); v.w = pack2(A6[6], A6[7]);
    *(uint4*)&g_A[1][pidx] = v;
    v.x = pack2(A7[0], A7[1]); v.y = pack2(A7[2], A7[3]);
    v.z = pack2(A7[4], A7[5]); v.w = pack2(A7[6], A7[7]);
    *(uint4*)&g_A[2][pidx] = v;
    v.x = pack2(A8[0], A8[1]); v.y = pack2(A8[2], A8[3]);
    v.z = pack2(A8[4], A8[5]); v.w = pack2(A8[6], A8[7]);
    *(uint4*)&g_A[3][pidx] = v;
    st8(pout + pidx, outv);
}

// ---------------------------------------------------------------------------
// One Jacobi iteration, 4 px/thread, padded layout: every load unconditional.
// S accumulated inline from the 8 loaded A values (OOB positions hold 1.0,
// matching exp(0); their message terms multiply pred=0).
// ---------------------------------------------------------------------------
__global__ __launch_bounds__(256)
void message_pass(const float* __restrict__ pin,
                  const float* __restrict__ unary,
                  const float* __restrict__ weight,
                  float* __restrict__ pout, int last)
{
    int q = blockIdx.x * 256 + threadIdx.x;          // quad index
    int w4 = (q & 127) << 2;
    int h  = (q >> 7) & (HH - 1);
    int b  = q >> 16;
    int uidx = b * HW + (h << 9) + w4;
    int pidx = b * IMG + FPAD + h * RSTR + w4;
    int up   = pidx - RSTR;
    float hw = 0.5f * __ldg(weight);

    // pred neighborhood: 3 rows x cols [w4-1 .. w4+4], all unconditional
    float row[3][6];
#pragma unroll
    for (int r = 0; r < 3; r++) {
        const float* p = pin + pidx + (r - 1) * RSTR;
        float4 v = *(const float4*)p;
        row[r][0] = p[-1];
        row[r][1] = v.x; row[r][2] = v.y; row[r][3] = v.z; row[r][4] = v.w;
        row[r][5] = p[4];
    }

    float acc[4], S[4];
#pragma unroll
    for (int j = 0; j < 4; j++) { acc[j] = AC * row[1][j + 1]; S[j] = AC; }

    const __half* P0 = g_A[0]; const __half* P1 = g_A[1];
    const __half* P2 = g_A[2]; const __half* P3 = g_A[3];

    {   // dir0 (0,+1) fwd / (0,-1) bwd — same row
        float f[4]; unpack4(__ldg((const uint2*)&P0[pidx]), f);
        float bm = h2f(__ldg((const u32*)&P0[pidx - 2])).y;   // A0[p-1]
#pragma unroll
        for (int j = 0; j < 4; j++) {
            float bw = (j > 0) ? f[j - 1] : bm;
            acc[j] += f[j] * row[1][j + 2] + bw * row[1][j];
            S[j]   += f[j] + bw;
        }
    }
    {   // dir1 (+1,-1) fwd / (-1,+1) bwd
        float f[4]; unpack4(__ldg((const uint2*)&P1[pidx]), f);
        float u[4]; unpack4(__ldg((const uint2*)&P1[up]), u);
        float e1 = h2f(__ldg((const u32*)&P1[up + 4])).x;     // A1[u+4]
#pragma unroll
        for (int j = 0; j < 4; j++) {
            float bw = (j < 3) ? u[j + 1] : e1;
            acc[j] += f[j] * row[2][j] + bw * row[0][j + 2];
            S[j]   += f[j] + bw;
        }
    }
    {   // dir2 (+1,0) fwd / (-1,0) bwd
        float f[4]; unpack4(__ldg((const uint2*)&P2[pidx]), f);
        float u[4]; unpack4(__ldg((const uint2*)&P2[up]), u);
#pragma unroll
        for (int j = 0; j < 4; j++) {
            acc[j] += f[j] * row[2][j + 1] + u[j] * row[0][j + 1];
            S[j]   += f[j] + u[j];
        }
    }
    {   // dir3 (+1,+1) fwd / (-1,-1) bwd
        float f[4]; unpack4(__ldg((const uint2*)&P3[pidx]), f);
        float u[4]; unpack4(__ldg((const uint2*)&P3[up]), u);
        float e3 = h2f(__ldg((const u32*)&P3[up - 2])).y;     // A3[u-1]
#pragma unroll
        for (int j = 0; j < 4; j++) {
            float bw = (j > 0) ? u[j - 1] : e3;
            acc[j] += f[j] * row[2][j + 2] + bw * row[0][j];
            S[j]   += f[j] + bw;
        }
    }

    float4 uv = __ldg((const float4*)(unary + uidx));
    float4 o;
    o.x = 0.5f * uv.x + __fdividef(hw, S[0]) * acc[0];
    o.y = 0.5f * uv.y + __fdividef(hw, S[1]) * acc[1];
    o.z = 0.5f * uv.z + __fdividef(hw, S[2]) * acc[2];
    o.w = 0.5f * uv.w + __fdividef(hw, S[3]) * acc[3];
    if (last) *(float4*)(pout + uidx) = o;
    else      *(float4*)(pout + pidx) = o;
}

extern "C" void kernel_launch(void* const* d_in, const int* in_sizes, int n_in,
                              void* d_out, int out_size)
{
    const float* image  = (const float*)d_in[0];
    const float* unary  = (const float*)d_in[1];
    const float* theta  = (const float*)d_in[2];
    const float* weight = (const float*)d_in[3];
    float* out = (float*)d_out;

    void* baddr = nullptr;
    cudaGetSymbolAddress(&baddr, g_buf);   // non-stream API: capture-safe
    float* buf0 = (float*)baddr;
    float* buf1 = buf0 + PTOT;

    init_pads<<<(BB * PADN + 255) / 256, 256>>>();
    build_kernel<<<(NPIX / 8) / 256, 256>>>(image, unary, theta, weight, buf0); // iter 1

    const int GRID = (NPIX / 4) / 256;     // 4096 blocks
    for (int i = 1; i < 10; i++) {         // iters 2..10
        float* pin  = (i & 1) ? buf0 : buf1;           // (i-1)%2
        float* pout = (i == 9) ? out : ((i & 1) ? buf1 : buf0);
        message_pass<<<GRID, 256>>>(pin, unary, weight, pout, i == 9);
    }
}

// round 16
// speedup vs baseline: 1.2508x; 1.1805x over previous
#include <cuda_runtime.h>
#include <cuda_fp16.h>
#include <cstdint>

#define BB    16
#define HH    512
#define WW    512
#define HW    (HH * WW)
#define NPIX  (BB * HW)

#define RSTR  520                       // padded row stride
#define FPAD  528                       // per-image front pad
#define BPAD  528                       // per-image back pad
#define IMG   (FPAD + HH * RSTR + BPAD)
#define PTOT  (BB * IMG)

typedef unsigned int u32;

// A planes: padded, plane-major; pads/gaps = 1.0 (OOB softmax entry = exp(0),
// so inline-S is exact at borders). Pred ping-pong + unary copy in fp16,
// padded; pred pads stay 0.0 (zero-initialized, never written) -> message
// terms at OOB multiply by pred=0: exact reference boundary semantics.
// Dirs: 0=(0,1) 1=(1,-1) 2=(1,0) 3=(1,1);  A = exp(entry), symmetric:
// A_d(p) == A_{-d}(p+d); center entry = exp(1).
__device__ __half g_A[4][PTOT];    // 34.2 MB
__device__ __half g_buf[2][PTOT];  // fp16 padded ping-pong pred buffers
__device__ __half g_uh[PTOT];      // fp16 unary copy (padded index)

#define AC 2.7182818284590452f     // exp(1): center softmax-numerator

// ---------------------------------------------------------------------------
__device__ __forceinline__ float2 h2f(const u32 u) {
    return __half22float2(*reinterpret_cast<const __half2*>(&u));
}
__device__ __forceinline__ u32 pack2(float a, float b) {
    __half2 h = __halves2half2(__float2half(a), __float2half(b));
    return *reinterpret_cast<u32*>(&h);
}
__device__ __forceinline__ void unpack4(const uint2 v, float* f) {
    float2 a = h2f(v.x), b = h2f(v.y);
    f[0] = a.x; f[1] = a.y; f[2] = b.x; f[3] = b.y;
}
// guarded row load for UNPADDED fp32 arrays (build inputs)
__device__ __forceinline__ void ldrow_g(const float* p, float* r, int w8) {
    float4 v0 = *(const float4*)p;
    float4 v1 = *(const float4*)(p + 4);
    r[0] = (w8 > 0)      ? p[-1] : 0.0f;
    r[1] = v0.x; r[2] = v0.y; r[3] = v0.z; r[4] = v0.w;
    r[5] = v1.x; r[6] = v1.y; r[7] = v1.z; r[8] = v1.w;
    r[9] = (w8 + 8 < WW) ? p[8]  : 0.0f;
}
// fp16 padded row load: r[0..5] = cols [c-1 .. c+4]  (all in-bounds via pads)
__device__ __forceinline__ void ldrow_h(const __half* hp, float* r) {
    u32  a = __ldg((const u32*) (hp - 2));   // cols -2,-1
    uint2 b = __ldg((const uint2*)(hp));      // cols 0..3
    u32  c = __ldg((const u32*) (hp + 4));   // cols 4,5
    r[0] = h2f(a).y;
    float2 b0 = h2f(b.x), b1 = h2f(b.y);
    r[1] = b0.x; r[2] = b0.y; r[3] = b1.x; r[4] = b1.y;
    r[5] = h2f(c).x;
}
__device__ __forceinline__ uint4 pack8(const float* o) {
    uint4 v;
    v.x = pack2(o[0], o[1]); v.y = pack2(o[2], o[3]);
    v.z = pack2(o[4], o[5]); v.w = pack2(o[6], o[7]);
    return v;
}

// ---------------------------------------------------------------------------
// Set A pads/gaps (front pad, per-row 8-elem gaps, back pad) to 1.0.
// ---------------------------------------------------------------------------
#define PADN (FPAD + HH * 8 + BPAD)     // pad elems per image
__global__ __launch_bounds__(256)
void init_pads()
{
    int e = blockIdx.x * 256 + threadIdx.x;
    if (e >= BB * PADN) return;
    int b = e / PADN, j = e - b * PADN;
    int off;
    if (j < FPAD)             off = j;
    else if (j < FPAD + HH*8) { int g = j - FPAD; off = FPAD + (g >> 3) * RSTR + WW + (g & 7); }
    else                      off = FPAD + HH * RSTR + (j - (FPAD + HH * 8));
    const __half one = __float2half(1.0f);
    int idx = b * IMG + off;
    g_A[0][idx] = one; g_A[1][idx] = one; g_A[2][idx] = one; g_A[3][idx] = one;
}

// ---------------------------------------------------------------------------
// Build pass + iteration 1, octet-per-thread. Also emits fp16 unary copy.
// ---------------------------------------------------------------------------
__global__ __launch_bounds__(256)
void build_kernel(const float* __restrict__ image,
                  const float* __restrict__ unary,
                  const float* __restrict__ theta,
                  const float* __restrict__ weight,
                  __half* __restrict__ pout)
{
    int t  = blockIdx.x * 256 + threadIdx.x;
    int w8 = (t & 63) << 3;
    int h  = (t >> 6) & (HH - 1);
    int b  = t >> 15;
    int uidx = b * HW + (h << 9) + w8;

    float t0 = theta[0], t1 = theta[1], t2 = theta[2];
    float hw = 0.5f * weight[0];

    float win[3][10], uwin[3][10];
    bool rowok[3];
#pragma unroll
    for (int r = 0; r < 3; r++) {
        int gh = h + r - 1;
        rowok[r] = (unsigned)gh < HH;
        if (!rowok[r]) {
#pragma unroll
            for (int c = 0; c < 10; c++) { win[r][c] = 0.f; uwin[r][c] = 0.f; }
        } else {
            ldrow_g(image + uidx + (r - 1) * WW, win[r],  w8);
            ldrow_g(unary + uidx + (r - 1) * WW, uwin[r], w8);
        }
    }

    float geo[9];
#pragma unroll
    for (int k = 0; k < 9; k++) {
        int dx = k / 3 - 1, dy = k % 3 - 1;
        geo[k] = t0 * (float)(dx * dx) + t1 * (float)(dy * dy);
    }

    float A5[8], A6[8], A7[8], A8[8], outv[8];
#pragma unroll
    for (int j = 0; j < 8; j++) {
        float cc = win[1][j + 1] * 255.f;
        float S = AC, msg = 0.f;
#pragma unroll
        for (int k = 0; k < 9; k++) {
            int dx = k / 3 - 1, dy = k % 3 - 1;
            bool ok = rowok[1 + dx];
            if (dy < 0) ok = ok && (w8 + j > 0);
            if (dy > 0) ok = ok && (w8 + j + 1 < WW);
            float nb = win[1 + dx][j + 1 + dy];
            float d  = nb * 255.f - cc;
            float e  = ok ? __expf(-0.5f * (geo[k] + t2 * d * d)) : 0.f;
            float Af = __expf(e);
            if (k != 4) S += __half2float(__float2half(Af));
            msg += Af * uwin[1 + dx][j + 1 + dy];   // OOB: 1 * 0 = 0
            if (k == 5) A5[j] = Af;
            if (k == 6) A6[j] = Af;
            if (k == 7) A7[j] = Af;
            if (k == 8) A8[j] = Af;
        }
        outv[j] = 0.5f * uwin[1][j + 1] + __fdividef(hw, S) * msg;
    }

    int pidx = b * IMG + FPAD + h * RSTR + w8;
    *(uint4*)&g_A[0][pidx] = pack8(A5);
    *(uint4*)&g_A[1][pidx] = pack8(A6);
    *(uint4*)&g_A[2][pidx] = pack8(A7);
    *(uint4*)&g_A[3][pidx] = pack8(A8);
    *(uint4*)&g_uh[pidx]   = pack8(&uwin[1][1]);    // fp16 unary copy
    *(uint4*)&pout[pidx]   = pack8(outv);           // iter-1 pred (fp16)
}

// ---------------------------------------------------------------------------
// One Jacobi iteration, 4 px/thread, fully unconditional loads (padded fp16
// pred, padded A with 1.0 pads, fp16 unary). Inline softmax denominator.
// ---------------------------------------------------------------------------
__global__ __launch_bounds__(256)
void message_pass(const __half* __restrict__ pin,
                  const float* __restrict__ weight,
                  float* __restrict__ fout,
                  __half* __restrict__ hout, int last)
{
    int q = blockIdx.x * 256 + threadIdx.x;          // quad index
    int w4 = (q & 127) << 2;
    int h  = (q >> 7) & (HH - 1);
    int b  = q >> 16;
    int pidx = b * IMG + FPAD + h * RSTR + w4;
    int up   = pidx - RSTR;
    float hw = 0.5f * __ldg(weight);

    // pred neighborhood: 3 rows x cols [w4-1 .. w4+4], all unconditional
    float row[3][6];
#pragma unroll
    for (int r = 0; r < 3; r++)
        ldrow_h(pin + pidx + (r - 1) * RSTR, row[r]);

    float acc[4], S[4];
#pragma unroll
    for (int j = 0; j < 4; j++) { acc[j] = AC * row[1][j + 1]; S[j] = AC; }

    const __half* P0 = g_A[0]; const __half* P1 = g_A[1];
    const __half* P2 = g_A[2]; const __half* P3 = g_A[3];

    {   // dir0 (0,+1) fwd / (0,-1) bwd — same row
        float f[4]; unpack4(__ldg((const uint2*)&P0[pidx]), f);
        float bm = h2f(__ldg((const u32*)&P0[pidx - 2])).y;   // A0[p-1]
#pragma unroll
        for (int j = 0; j < 4; j++) {
            float bw = (j > 0) ? f[j - 1] : bm;
            acc[j] += f[j] * row[1][j + 2] + bw * row[1][j];
            S[j]   += f[j] + bw;
        }
    }
    {   // dir1 (+1,-1) fwd / (-1,+1) bwd
        float f[4]; unpack4(__ldg((const uint2*)&P1[pidx]), f);
        float u[4]; unpack4(__ldg((const uint2*)&P1[up]), u);
        float e1 = h2f(__ldg((const u32*)&P1[up + 4])).x;     // A1[u+4]
#pragma unroll
        for (int j = 0; j < 4; j++) {
            float bw = (j < 3) ? u[j + 1] : e1;
            acc[j] += f[j] * row[2][j] + bw * row[0][j + 2];
            S[j]   += f[j] + bw;
        }
    }
    {   // dir2 (+1,0) fwd / (-1,0) bwd
        float f[4]; unpack4(__ldg((const uint2*)&P2[pidx]), f);
        float u[4]; unpack4(__ldg((const uint2*)&P2[up]), u);
#pragma unroll
        for (int j = 0; j < 4; j++) {
            acc[j] += f[j] * row[2][j + 1] + u[j] * row[0][j + 1];
            S[j]   += f[j] + u[j];
        }
    }
    {   // dir3 (+1,+1) fwd / (-1,-1) bwd
        float f[4]; unpack4(__ldg((const uint2*)&P3[pidx]), f);
        float u[4]; unpack4(__ldg((const uint2*)&P3[up]), u);
        float e3 = h2f(__ldg((const u32*)&P3[up - 2])).y;     // A3[u-1]
#pragma unroll
        for (int j = 0; j < 4; j++) {
            float bw = (j > 0) ? u[j - 1] : e3;
            acc[j] += f[j] * row[2][j + 2] + bw * row[0][j];
            S[j]   += f[j] + bw;
        }
    }

    float uv[4]; unpack4(__ldg((const uint2*)&g_uh[pidx]), uv);
    float o[4];
#pragma unroll
    for (int j = 0; j < 4; j++)
        o[j] = 0.5f * uv[j] + __fdividef(hw, S[j]) * acc[j];

    if (last) {
        int uidx = b * HW + (h << 9) + w4;
        *(float4*)(fout + uidx) = make_float4(o[0], o[1], o[2], o[3]);
    } else {
        uint2 v; v.x = pack2(o[0], o[1]); v.y = pack2(o[2], o[3]);
        *(uint2*)&hout[pidx] = v;
    }
}

extern "C" void kernel_launch(void* const* d_in, const int* in_sizes, int n_in,
                              void* d_out, int out_size)
{
    const float* image  = (const float*)d_in[0];
    const float* unary  = (const float*)d_in[1];
    const float* theta  = (const float*)d_in[2];
    const float* weight = (const float*)d_in[3];
    float* out = (float*)d_out;

    void* baddr = nullptr;
    cudaGetSymbolAddress(&baddr, g_buf);   // non-stream API: capture-safe
    __half* buf0 = (__half*)baddr;
    __half* buf1 = buf0 + PTOT;

    init_pads<<<(BB * PADN + 255) / 256, 256>>>();
    build_kernel<<<(NPIX / 8) / 256, 256>>>(image, unary, theta, weight, buf0); // iter 1

    const int GRID = (NPIX / 4) / 256;     // 4096 blocks
    for (int i = 1; i < 10; i++) {         // iters 2..10
        __half* pin  = (i & 1) ? buf0 : buf1;
        __half* hout = (i & 1) ? buf1 : buf0;
        message_pass<<<GRID, 256>>>(pin, weight, out, hout, i == 9);
    }
}

// round 17
// speedup vs baseline: 1.2535x; 1.0022x over previous
#include <cuda_runtime.h>
#include <cuda_fp16.h>
#include <cstdint>

#define BB    16
#define HH    512
#define WW    512
#define HW    (HH * WW)
#define NPIX  (BB * HW)

#define RSTR  520                       // padded row stride
#define FPAD  528                       // per-image front pad
#define BPAD  528                       // per-image back pad
#define IMG   (FPAD + HH * RSTR + BPAD)
#define PTOT  (BB * IMG)

typedef unsigned int u32;

// A planes: padded, plane-major; pads/gaps = 1.0 (OOB softmax entry = exp(0),
// so inline-S is exact at borders). Pred ping-pong + unary copy in fp16,
// padded; pred pads stay 0.0 (zero-initialized, never written) -> message
// terms at OOB multiply by pred=0: exact reference boundary semantics.
// Dirs: 0=(0,1) 1=(1,-1) 2=(1,0) 3=(1,1);  A = exp(entry), symmetric:
// A_d(p) == A_{-d}(p+d); center entry = exp(1).
__device__ __half g_A[4][PTOT];    // 34.2 MB
__device__ __half g_buf[2][PTOT];  // fp16 padded ping-pong pred buffers
__device__ __half g_uh[PTOT];      // fp16 unary copy (padded index)

#define AC 2.7182818284590452f     // exp(1): center softmax-numerator

// ---------------------------------------------------------------------------
__device__ __forceinline__ float2 h2f(const u32 u) {
    return __half22float2(*reinterpret_cast<const __half2*>(&u));
}
__device__ __forceinline__ u32 pack2(float a, float b) {
    __half2 h = __halves2half2(__float2half(a), __float2half(b));
    return *reinterpret_cast<u32*>(&h);
}
__device__ __forceinline__ void unpack8(const uint4 v, float* f) {
    float2 a = h2f(v.x), b = h2f(v.y), c = h2f(v.z), d = h2f(v.w);
    f[0] = a.x; f[1] = a.y; f[2] = b.x; f[3] = b.y;
    f[4] = c.x; f[5] = c.y; f[6] = d.x; f[7] = d.y;
}
// guarded row load for UNPADDED fp32 arrays (build inputs)
__device__ __forceinline__ void ldrow_g(const float* p, float* r, int w8) {
    float4 v0 = *(const float4*)p;
    float4 v1 = *(const float4*)(p + 4);
    r[0] = (w8 > 0)      ? p[-1] : 0.0f;
    r[1] = v0.x; r[2] = v0.y; r[3] = v0.z; r[4] = v0.w;
    r[5] = v1.x; r[6] = v1.y; r[7] = v1.z; r[8] = v1.w;
    r[9] = (w8 + 8 < WW) ? p[8]  : 0.0f;
}
// fp16 padded row load, 8 px + edges: r[0..9] = cols [c-1 .. c+8]
__device__ __forceinline__ void ldrow_h8(const __half* hp, float* r) {
    u32   a = __ldg((const u32*) (hp - 2));   // cols -2,-1
    uint4 b = __ldg((const uint4*)(hp));       // cols 0..7
    u32   c = __ldg((const u32*) (hp + 8));   // cols 8,9
    r[0] = h2f(a).y;
    unpack8(b, r + 1);
    r[9] = h2f(c).x;
}
__device__ __forceinline__ uint4 pack8v(const float* o) {
    uint4 v;
    v.x = pack2(o[0], o[1]); v.y = pack2(o[2], o[3]);
    v.z = pack2(o[4], o[5]); v.w = pack2(o[6], o[7]);
    return v;
}

// ---------------------------------------------------------------------------
// Set A pads/gaps (front pad, per-row 8-elem gaps, back pad) to 1.0.
// ---------------------------------------------------------------------------
#define PADN (FPAD + HH * 8 + BPAD)     // pad elems per image
__global__ __launch_bounds__(256)
void init_pads()
{
    int e = blockIdx.x * 256 + threadIdx.x;
    if (e >= BB * PADN) return;
    int b = e / PADN, j = e - b * PADN;
    int off;
    if (j < FPAD)             off = j;
    else if (j < FPAD + HH*8) { int g = j - FPAD; off = FPAD + (g >> 3) * RSTR + WW + (g & 7); }
    else                      off = FPAD + HH * RSTR + (j - (FPAD + HH * 8));
    const __half one = __float2half(1.0f);
    int idx = b * IMG + off;
    g_A[0][idx] = one; g_A[1][idx] = one; g_A[2][idx] = one; g_A[3][idx] = one;
}

// ---------------------------------------------------------------------------
// Build pass + iteration 1, octet-per-thread. Also emits fp16 unary copy.
// ---------------------------------------------------------------------------
__global__ __launch_bounds__(256)
void build_kernel(const float* __restrict__ image,
                  const float* __restrict__ unary,
                  const float* __restrict__ theta,
                  const float* __restrict__ weight,
                  __half* __restrict__ pout)
{
    int t  = blockIdx.x * 256 + threadIdx.x;
    int w8 = (t & 63) << 3;
    int h  = (t >> 6) & (HH - 1);
    int b  = t >> 15;
    int uidx = b * HW + (h << 9) + w8;

    float t0 = theta[0], t1 = theta[1], t2 = theta[2];
    float hw = 0.5f * weight[0];

    float win[3][10], uwin[3][10];
    bool rowok[3];
#pragma unroll
    for (int r = 0; r < 3; r++) {
        int gh = h + r - 1;
        rowok[r] = (unsigned)gh < HH;
        if (!rowok[r]) {
#pragma unroll
            for (int c = 0; c < 10; c++) { win[r][c] = 0.f; uwin[r][c] = 0.f; }
        } else {
            ldrow_g(image + uidx + (r - 1) * WW, win[r],  w8);
            ldrow_g(unary + uidx + (r - 1) * WW, uwin[r], w8);
        }
    }

    float geo[9];
#pragma unroll
    for (int k = 0; k < 9; k++) {
        int dx = k / 3 - 1, dy = k % 3 - 1;
        geo[k] = t0 * (float)(dx * dx) + t1 * (float)(dy * dy);
    }

    float A5[8], A6[8], A7[8], A8[8], outv[8];
#pragma unroll
    for (int j = 0; j < 8; j++) {
        float cc = win[1][j + 1] * 255.f;
        float S = AC, msg = 0.f;
#pragma unroll
        for (int k = 0; k < 9; k++) {
            int dx = k / 3 - 1, dy = k % 3 - 1;
            bool ok = rowok[1 + dx];
            if (dy < 0) ok = ok && (w8 + j > 0);
            if (dy > 0) ok = ok && (w8 + j + 1 < WW);
            float nb = win[1 + dx][j + 1 + dy];
            float d  = nb * 255.f - cc;
            float e  = ok ? __expf(-0.5f * (geo[k] + t2 * d * d)) : 0.f;
            float Af = __expf(e);
            if (k != 4) S += __half2float(__float2half(Af));
            msg += Af * uwin[1 + dx][j + 1 + dy];   // OOB: 1 * 0 = 0
            if (k == 5) A5[j] = Af;
            if (k == 6) A6[j] = Af;
            if (k == 7) A7[j] = Af;
            if (k == 8) A8[j] = Af;
        }
        outv[j] = 0.5f * uwin[1][j + 1] + __fdividef(hw, S) * msg;
    }

    int pidx = b * IMG + FPAD + h * RSTR + w8;
    *(uint4*)&g_A[0][pidx] = pack8v(A5);
    *(uint4*)&g_A[1][pidx] = pack8v(A6);
    *(uint4*)&g_A[2][pidx] = pack8v(A7);
    *(uint4*)&g_A[3][pidx] = pack8v(A8);
    *(uint4*)&g_uh[pidx]   = pack8v(&uwin[1][1]);   // fp16 unary copy
    *(uint4*)&pout[pidx]   = pack8v(outv);          // iter-1 pred (fp16)
}

// ---------------------------------------------------------------------------
// One Jacobi iteration, 8 px/thread, fully unconditional loads (padded fp16
// pred, padded A with 1.0 pads, fp16 unary). Inline softmax denominator.
// ---------------------------------------------------------------------------
__global__ __launch_bounds__(256)
void message_pass(const __half* __restrict__ pin,
                  const float* __restrict__ weight,
                  float* __restrict__ fout,
                  __half* __restrict__ hout, int last)
{
    int t  = blockIdx.x * 256 + threadIdx.x;        // octet index
    int w8 = (t & 63) << 3;
    int h  = (t >> 6) & (HH - 1);
    int b  = t >> 15;
    int pidx = b * IMG + FPAD + h * RSTR + w8;
    int up   = pidx - RSTR;
    float hw = 0.5f * __ldg(weight);

    const __half* P0 = g_A[0]; const __half* P1 = g_A[1];
    const __half* P2 = g_A[2]; const __half* P3 = g_A[3];

    // pred neighborhood: 3 rows x cols [w8-1 .. w8+8], all unconditional
    float row[3][10];
#pragma unroll
    for (int r = 0; r < 3; r++)
        ldrow_h8(pin + pidx + (r - 1) * RSTR, row[r]);

    float acc[8], S[8];
#pragma unroll
    for (int j = 0; j < 8; j++) { acc[j] = AC * row[1][j + 1]; S[j] = AC; }

    {   // dir0 (0,+1) fwd / (0,-1) bwd — same row
        float f[8]; unpack8(__ldg((const uint4*)&P0[pidx]), f);
        float bm = h2f(__ldg((const u32*)&P0[pidx - 2])).y;   // A0[p-1]
#pragma unroll
        for (int j = 0; j < 8; j++) {
            float bw = (j > 0) ? f[j - 1] : bm;
            acc[j] += f[j] * row[1][j + 2] + bw * row[1][j];
            S[j]   += f[j] + bw;
        }
    }
    {   // dir1 (+1,-1) fwd / (-1,+1) bwd
        float f[8]; unpack8(__ldg((const uint4*)&P1[pidx]), f);
        float u[8]; unpack8(__ldg((const uint4*)&P1[up]), u);
        float e1 = h2f(__ldg((const u32*)&P1[up + 8])).x;     // A1[u+8]
#pragma unroll
        for (int j = 0; j < 8; j++) {
            float bw = (j < 7) ? u[j + 1] : e1;
            acc[j] += f[j] * row[2][j] + bw * row[0][j + 2];
            S[j]   += f[j] + bw;
        }
    }
    {   // dir2 (+1,0) fwd / (-1,0) bwd
        float f[8]; unpack8(__ldg((const uint4*)&P2[pidx]), f);
        float u[8]; unpack8(__ldg((const uint4*)&P2[up]), u);
#pragma unroll
        for (int j = 0; j < 8; j++) {
            acc[j] += f[j] * row[2][j + 1] + u[j] * row[0][j + 1];
            S[j]   += f[j] + u[j];
        }
    }
    {   // dir3 (+1,+1) fwd / (-1,-1) bwd
        float f[8]; unpack8(__ldg((const uint4*)&P3[pidx]), f);
        float u[8]; unpack8(__ldg((const uint4*)&P3[up]), u);
        float e3 = h2f(__ldg((const u32*)&P3[up - 2])).y;     // A3[u-1]
#pragma unroll
        for (int j = 0; j < 8; j++) {
            float bw = (j > 0) ? u[j - 1] : e3;
            acc[j] += f[j] * row[2][j + 2] + bw * row[0][j];
            S[j]   += f[j] + bw;
        }
    }

    float uv[8]; unpack8(__ldg((const uint4*)&g_uh[pidx]), uv);
    float o[8];
#pragma unroll
    for (int j = 0; j < 8; j++)
        o[j] = 0.5f * uv[j] + __fdividef(hw, S[j]) * acc[j];

    if (last) {
        int uidx = b * HW + (h << 9) + w8;
        *(float4*)(fout + uidx)     = make_float4(o[0], o[1], o[2], o[3]);
        *(float4*)(fout + uidx + 4) = make_float4(o[4], o[5], o[6], o[7]);
    } else {
        *(uint4*)&hout[pidx] = pack8v(o);
    }
}

extern "C" void kernel_launch(void* const* d_in, const int* in_sizes, int n_in,
                              void* d_out, int out_size)
{
    const float* image  = (const float*)d_in[0];
    const float* unary  = (const float*)d_in[1];
    const float* theta  = (const float*)d_in[2];
    const float* weight = (const float*)d_in[3];
    float* out = (float*)d_out;

    void* baddr = nullptr;
    cudaGetSymbolAddress(&baddr, g_buf);   // non-stream API: capture-safe
    __half* buf0 = (__half*)baddr;
    __half* buf1 = buf0 + PTOT;

    init_pads<<<(BB * PADN + 255) / 256, 256>>>();
    build_kernel<<<(NPIX / 8) / 256, 256>>>(image, unary, theta, weight, buf0); // iter 1

    const int GRID = (NPIX / 8) / 256;     // 2048 blocks
    for (int i = 1; i < 10; i++) {         // iters 2..10
        __half* pin  = (i & 1) ? buf0 : buf1;
        __half* hout = (i & 1) ? buf1 : buf0;
        message_pass<<<GRID, 256>>>(pin, weight, out, hout, i == 9);
    }
}